// round 8
// baseline (speedup 1.0000x reference)
#include <cuda_runtime.h>
#include <cuda_bf16.h>

#define O_CH  256
#define C_IN  128
#define KH_N  24
#define N_IN  24
#define N_OUT 24
#define KS    5
#define VOL   (KS*KS*KS)                          // 125
#define WH_SIZE ((size_t)O_CH*N_IN*C_IN*N_OUT)    // 18,874,368
#define A_GRP 3                                   // a's per gather block
#define NB_WH (O_CH * (N_IN / A_GRP))             // 2048 gather blocks
#define NB_RN O_CH                                // 256 wrn blocks
#define APITCH (C_IN * N_OUT)                     // 3072 floats per (o,a)
#define SWS 25                                    // padded smem row stride (odd)

// ---------------------------------------------------------------------------
// Single fused kernel.
// Gather blocks (o, 3 a's): stage weight_H[o] at stride-25 in smem, compute
// the 3x24 nn indices inline, then emit float4 gathers:
//   4 LDS.32 + 1 LDS.128 (int4 indices) + 1 STG.128 per 16B of output.
// wRn blocks: trilinear resample, one block per o.
// ---------------------------------------------------------------------------
__global__ void __launch_bounds__(256) fused_kernel(
        const float* __restrict__ in_H,      // [24,3,3]
        const float* __restrict__ out_H,     // [24,3,3]
        const float* __restrict__ grid_H,    // [24,3,3]
        const float* __restrict__ grid_Rn,   // [3,5,5,5]
        const float* __restrict__ weight_H,  // [256,128,24]
        const float* __restrict__ weight_Rn, // [256,1,5,5,5]
        float* __restrict__ out) {
    const int idx = blockIdx.x;
    const int t = threadIdx.x;

    if (idx < NB_WH) {
        // ================= wH gather =================
        __shared__ float sw[C_IN * SWS];         // 12.8 KB, stride-25 rows
        __shared__ float sOH[216], sGH[216], sIH[A_GRP * 9];
        __shared__ __align__(16) int snn[A_GRP * N_OUT];   // 72 indices

        const int o  = idx >> 3;                 // idx / 8
        const int a0 = (idx & 7) * A_GRP;

        // stage weights: float4 LDG (coalesced) -> 4 scalar STS (stride 25)
        const float4* wsrc = reinterpret_cast<const float4*>(
            weight_H + (size_t)o * C_IN * KH_N);
#pragma unroll
        for (int i = 0; i < 3; i++) {
            const int j4 = 256 * i + t;          // 0..767
            const float4 v = wsrc[j4];
            const int c = j4 / 6, q = j4 % 6;
            float* dstr = sw + c * SWS + q * 4;
            dstr[0] = v.x; dstr[1] = v.y; dstr[2] = v.z; dstr[3] = v.w;
        }
        if (t < 216) { sOH[t] = out_H[t]; sGH[t] = grid_H[t]; }
        if (t < A_GRP * 9) sIH[t] = in_H[a0 * 9 + t];
        __syncthreads();

        // inline nn argmax: thread t<72 handles (a = a0 + t/24, b = t%24)
        if (t < A_GRP * N_OUT) {
            const int al = t / N_OUT, b = t % N_OUT;
            float P[9];
#pragma unroll
            for (int i = 0; i < 3; i++)
#pragma unroll
                for (int j = 0; j < 3; j++) {
                    float s = 0.f;
#pragma unroll
                    for (int k = 0; k < 3; k++)
                        s += sOH[b * 9 + k * 3 + i] * sIH[al * 9 + k * 3 + j];
                    P[i * 3 + j] = s;
                }
            float best = -1e30f; int bi = 0;
            for (int kh = 0; kh < KH_N; kh++) {
                float s = 0.f;
#pragma unroll
                for (int i = 0; i < 9; i++) s += P[i] * sGH[kh * 9 + i];
                if (s > best) { best = s; bi = kh; }   // strict > = first max
            }
            snn[t] = bi;
        }
        __syncthreads();

        const int4* snn4 = reinterpret_cast<const int4*>(snn);  // [3][6]
        float4* dst = reinterpret_cast<float4*>(out)
                    + ((size_t)o * N_IN + a0) * (APITCH / 4);

#pragma unroll
        for (int i = 0; i < 3; i++) {
            const int j = 256 * i + t;           // float4 index 0..767
            const int c = j / 6, q = j % 6;
            const float* row = sw + c * SWS;
#pragma unroll
            for (int al = 0; al < A_GRP; al++) {
                const int4 n4 = snn4[al * 6 + q];
                float4 v;
                v.x = row[n4.x];
                v.y = row[n4.y];
                v.z = row[n4.z];
                v.w = row[n4.w];
                dst[al * (APITCH / 4) + j] = v;
            }
        }
    } else {
        // ================= wRn trilinear =================
        __shared__ float vol[VOL];
        __shared__ float R[216];
        __shared__ float sg[3 * VOL];
        const int o = idx - NB_WH;
        if (t < VOL) vol[t] = weight_Rn[(size_t)o * VOL + t];
        if (t < 216) R[t]   = out_H[t];
        for (int i = t; i < 3 * VOL; i += 256) sg[i] = grid_Rn[i];
        __syncthreads();

#pragma unroll
        for (int f = t; f < N_OUT * VOL; f += 256) {
            const int b = f / VOL;
            const int p = f % VOL;
            const float* Rb = R + b * 9;

            const float g0 = sg[p], g1 = sg[VOL + p], g2 = sg[2 * VOL + p];
            float cz = Rb[0] * g0 + Rb[3] * g1 + Rb[6] * g2;
            float cy = Rb[1] * g0 + Rb[4] * g1 + Rb[7] * g2;
            float cx = Rb[2] * g0 + Rb[5] * g1 + Rb[8] * g2;
            cz = (cz + 1.f) * 0.5f * (KS - 1);
            cy = (cy + 1.f) * 0.5f * (KS - 1);
            cx = (cx + 1.f) * 0.5f * (KS - 1);

            const float z0f = floorf(cz), y0f = floorf(cy), x0f = floorf(cx);
            const int z0 = (int)z0f, y0 = (int)y0f, x0 = (int)x0f;
            const float fz = cz - z0f, fy = cy - y0f, fx = cx - x0f;

            float acc = 0.f;
#pragma unroll
            for (int dz = 0; dz < 2; dz++)
#pragma unroll
                for (int dy = 0; dy < 2; dy++)
#pragma unroll
                    for (int dx = 0; dx < 2; dx++) {
                        const int iz = z0 + dz, iy = y0 + dy, ix = x0 + dx;
                        const bool valid = (iz >= 0) & (iz < KS) & (iy >= 0) & (iy < KS)
                                         & (ix >= 0) & (ix < KS);
                        const int ci = min(max(iz, 0), KS - 1) * 25
                                     + min(max(iy, 0), KS - 1) * 5
                                     + min(max(ix, 0), KS - 1);
                        const float w = (dz ? fz : 1.f - fz) * (dy ? fy : 1.f - fy)
                                      * (dx ? fx : 1.f - fx);
                        acc += (valid ? vol[ci] : 0.f) * w;
                    }

            out[WH_SIZE + (size_t)o * (N_OUT * VOL) + f] = acc;
        }
    }
}

// ---------------------------------------------------------------------------
extern "C" void kernel_launch(void* const* d_in, const int* in_sizes, int n_in,
                              void* d_out, int out_size) {
    const float* in_H      = (const float*)d_in[0];
    const float* out_H     = (const float*)d_in[1];
    const float* grid_H    = (const float*)d_in[2];
    const float* grid_Rn   = (const float*)d_in[3];
    const float* weight_H  = (const float*)d_in[4];
    const float* weight_Rn = (const float*)d_in[5];
    float* out = (float*)d_out;

    fused_kernel<<<NB_WH + NB_RN, 256>>>(
        in_H, out_H, grid_H, grid_Rn, weight_H, weight_Rn, out);
}

// round 10
// speedup vs baseline: 1.2475x; 1.2475x over previous
#include <cuda_runtime.h>
#include <cuda_bf16.h>

#define O_CH  256
#define C_IN  128
#define KH_N  24
#define N_IN  24
#define N_OUT 24
#define KS    5
#define VOL   (KS*KS*KS)                          // 125
#define WH_SIZE ((size_t)O_CH*N_IN*C_IN*N_OUT)    // 18,874,368
#define A_GRP 4                                   // a's per gather block
#define NB_WH (O_CH * (N_IN / A_GRP))             // 1536 gather blocks
#define NB_RN O_CH                                // 256 wrn blocks (scheduled first)
#define APITCH (C_IN * N_OUT)                     // 3072 floats per (o,a)

// ---------------------------------------------------------------------------
// Single fused kernel. Blocks [0, NB_RN): wRn trilinear (light, run first).
// Blocks [NB_RN, NB_RN+NB_WH): wH gather via warp shuffle:
//   row weight_H[o,c,:] lives in lanes 0..23; out row = one SHFL per a.
// ---------------------------------------------------------------------------
__global__ void __launch_bounds__(256) fused_kernel(
        const float* __restrict__ in_H,      // [24,3,3]
        const float* __restrict__ out_H,     // [24,3,3]
        const float* __restrict__ grid_H,    // [24,3,3]
        const float* __restrict__ grid_Rn,   // [3,5,5,5]
        const float* __restrict__ weight_H,  // [256,128,24]
        const float* __restrict__ weight_Rn, // [256,1,5,5,5]
        float* __restrict__ out) {
    const int idx = blockIdx.x;
    const int t = threadIdx.x;

    if (idx >= NB_RN) {
        // ================= wH gather =================
        __shared__ float sw[C_IN * KH_N];     // 12 KB weights (stride 24)
        __shared__ float sOH[216], sGH[216], sIH[A_GRP * 9];
        __shared__ int   snn[A_GRP * N_OUT];  // 96 indices

        const int gidx = idx - NB_RN;
        const int o  = gidx / (N_IN / A_GRP);
        const int a0 = (gidx % (N_IN / A_GRP)) * A_GRP;

        const float4* wsrc = reinterpret_cast<const float4*>(
            weight_H + (size_t)o * C_IN * KH_N);
#pragma unroll
        for (int j = t; j < 768; j += 256)
            reinterpret_cast<float4*>(sw)[j] = wsrc[j];
        if (t < 216) { sOH[t] = out_H[t]; sGH[t] = grid_H[t]; }
        if (t < A_GRP * 9) sIH[t] = in_H[a0 * 9 + t];
        __syncthreads();

        // inline nn argmax: thread t<96 handles (a = a0 + t/24, b = t%24)
        if (t < A_GRP * N_OUT) {
            const int al = t / N_OUT, b = t % N_OUT;
            float P[9];
#pragma unroll
            for (int i = 0; i < 3; i++)
#pragma unroll
                for (int j = 0; j < 3; j++) {
                    float s = 0.f;
#pragma unroll
                    for (int k = 0; k < 3; k++)
                        s += sOH[b * 9 + k * 3 + i] * sIH[al * 9 + k * 3 + j];
                    P[i * 3 + j] = s;
                }
            float best = -1e30f; int bi = 0;
            for (int kh = 0; kh < KH_N; kh++) {
                float s = 0.f;
#pragma unroll
                for (int i = 0; i < 9; i++) s += P[i] * sGH[kh * 9 + i];
                if (s > best) { best = s; bi = kh; }   // strict > = first max
            }
            snn[t] = bi;
        }
        __syncthreads();

        const int lane = t & 31;
        const int wrp  = t >> 5;              // 8 warps
        const int ln   = (lane < N_OUT) ? lane : 0;

        int idxr[A_GRP];
#pragma unroll
        for (int al = 0; al < A_GRP; al++) idxr[al] = snn[al * N_OUT + ln];

        float* outo = out + ((size_t)o * N_IN + a0) * APITCH;

        // each warp handles rows c = wrp, wrp+8, ... (16 rows)
#pragma unroll 8
        for (int c = wrp; c < C_IN; c += 8) {
            const float wv = sw[c * KH_N + ln];
            float* rowdst = outo + c * N_OUT + lane;
#pragma unroll
            for (int al = 0; al < A_GRP; al++) {
                const float v = __shfl_sync(0xffffffffu, wv, idxr[al]);
                if (lane < N_OUT) rowdst[al * APITCH] = v;
            }
        }
    } else {
        // ================= wRn trilinear =================
        __shared__ float vol[VOL];
        __shared__ float R[216];
        __shared__ float sg[3 * VOL];
        const int o = idx;
        if (t < VOL) vol[t] = weight_Rn[(size_t)o * VOL + t];
        if (t < 216) R[t]   = out_H[t];
        for (int i = t; i < 3 * VOL; i += 256) sg[i] = grid_Rn[i];
        __syncthreads();

#pragma unroll
        for (int f = t; f < N_OUT * VOL; f += 256) {
            const int b = f / VOL;
            const int p = f % VOL;
            const float* Rb = R + b * 9;

            const float g0 = sg[p], g1 = sg[VOL + p], g2 = sg[2 * VOL + p];
            float cz = Rb[0] * g0 + Rb[3] * g1 + Rb[6] * g2;
            float cy = Rb[1] * g0 + Rb[4] * g1 + Rb[7] * g2;
            float cx = Rb[2] * g0 + Rb[5] * g1 + Rb[8] * g2;
            cz = (cz + 1.f) * 0.5f * (KS - 1);
            cy = (cy + 1.f) * 0.5f * (KS - 1);
            cx = (cx + 1.f) * 0.5f * (KS - 1);

            const float z0f = floorf(cz), y0f = floorf(cy), x0f = floorf(cx);
            const int z0 = (int)z0f, y0 = (int)y0f, x0 = (int)x0f;
            const float fz = cz - z0f, fy = cy - y0f, fx = cx - x0f;

            float acc = 0.f;
#pragma unroll
            for (int dz = 0; dz < 2; dz++)
#pragma unroll
                for (int dy = 0; dy < 2; dy++)
#pragma unroll
                    for (int dx = 0; dx < 2; dx++) {
                        const int iz = z0 + dz, iy = y0 + dy, ix = x0 + dx;
                        const bool valid = (iz >= 0) & (iz < KS) & (iy >= 0) & (iy < KS)
                                         & (ix >= 0) & (ix < KS);
                        const int ci = min(max(iz, 0), KS - 1) * 25
                                     + min(max(iy, 0), KS - 1) * 5
                                     + min(max(ix, 0), KS - 1);
                        const float w = (dz ? fz : 1.f - fz) * (dy ? fy : 1.f - fy)
                                      * (dx ? fx : 1.f - fx);
                        acc += (valid ? vol[ci] : 0.f) * w;
                    }

            out[WH_SIZE + (size_t)o * (N_OUT * VOL) + f] = acc;
        }
    }
}

// ---------------------------------------------------------------------------
extern "C" void kernel_launch(void* const* d_in, const int* in_sizes, int n_in,
                              void* d_out, int out_size) {
    const float* in_H      = (const float*)d_in[0];
    const float* out_H     = (const float*)d_in[1];
    const float* grid_H    = (const float*)d_in[2];
    const float* grid_Rn   = (const float*)d_in[3];
    const float* weight_H  = (const float*)d_in[4];
    const float* weight_Rn = (const float*)d_in[5];
    float* out = (float*)d_out;

    fused_kernel<<<NB_RN + NB_WH, 256>>>(
        in_H, out_H, grid_H, grid_Rn, weight_H, weight_Rn, out);
}